// round 2
// baseline (speedup 1.0000x reference)
#include <cuda_runtime.h>
#include <cstdint>

// Problem constants
#define D_DIM 768
#define M_DIM 640      // L*B*T = 2*16*20
#define V_DIM 30000

// Scratch (no allocation allowed -> __device__ globals)
__device__ float g_Wt[D_DIM * D_DIM];   // W transposed: Wt[k][d] = W[d][k]
__device__ float g_Ap[M_DIM * D_DIM];   // A' = A @ W
__device__ float g_s[M_DIM];            // s  = A @ b

// ---------------------------------------------------------------------------
// W transpose: Wt[k][d] = W[d][k]    (768x768)
// ---------------------------------------------------------------------------
__global__ void transpose_k(const float* __restrict__ W, float* __restrict__ Wt) {
    __shared__ float t[32][33];
    const int bx = blockIdx.x * 32, by = blockIdx.y * 32;
    const int x = threadIdx.x;
    #pragma unroll
    for (int j = threadIdx.y; j < 32; j += 8)
        t[j][x] = W[(by + j) * D_DIM + bx + x];
    __syncthreads();
    #pragma unroll
    for (int j = threadIdx.y; j < 32; j += 8)
        Wt[(bx + j) * D_DIM + by + x] = t[x][j];
}

// ---------------------------------------------------------------------------
// s[m] = sum_d A[m][d] * b[d]   (one warp per row)
// ---------------------------------------------------------------------------
__global__ void rowdot_k(const float* __restrict__ A, const float* __restrict__ b,
                         float* __restrict__ s) {
    const int m = blockIdx.x * 8 + (threadIdx.x >> 5);
    const int lane = threadIdx.x & 31;
    float acc = 0.f;
    #pragma unroll
    for (int d = lane; d < D_DIM; d += 32) acc += A[m * D_DIM + d] * b[d];
    #pragma unroll
    for (int o = 16; o; o >>= 1) acc += __shfl_xor_sync(0xffffffffu, acc, o);
    if (lane == 0) s[m] = acc;
}

// ---------------------------------------------------------------------------
// Generic GEMM: C[m][n] = sum_k A[m][k] * B[n][k]  (+ bias[m] if bias != null)
// A row-major [M,K], B row-major [N,K], C row-major [M,N].
// tf32 mma.sync (m16n8k8) with RNA conversion; 128x128x32 tiles,
// cp.async double buffering; padded smem (stride 36) -> conflict-free frags.
// ---------------------------------------------------------------------------
#define BM 128
#define BN 128
#define BK 32
#define LDSS 36   // smem row stride in floats (36*4 bytes, %16==0, %32==4 -> conflict free)

__device__ __forceinline__ uint32_t f2tf(float f) {
    uint32_t r;
    asm("cvt.rna.tf32.f32 %0, %1;" : "=r"(r) : "f"(f));
    return r;
}

__device__ __forceinline__ void cpasync16(uint32_t saddr, const void* g, int srcsz) {
    asm volatile("cp.async.cg.shared.global [%0], [%1], 16, %2;\n"
                 :: "r"(saddr), "l"(g), "r"(srcsz) : "memory");
}

__global__ __launch_bounds__(256, 2) void gemm_tf32_k(
    const float* __restrict__ A, const float* __restrict__ B,
    float* __restrict__ C, const float* __restrict__ bias,
    int M, int N, int K)
{
    extern __shared__ float smem[];
    float* As = smem;                       // [2][BM*LDSS]
    float* Bs = smem + 2 * BM * LDSS;       // [2][BN*LDSS]

    const int tid = threadIdx.x;
    const int m0 = blockIdx.x * BM;
    const int n0 = blockIdx.y * BN;
    const int KT = K / BK;

    const uint32_t sAs = (uint32_t)__cvta_generic_to_shared(As);
    const uint32_t sBs = (uint32_t)__cvta_generic_to_shared(Bs);

    const int lane = tid & 31;
    const int wid  = tid >> 5;
    const int wm = wid & 3;          // 4 warp-rows
    const int wn = wid >> 2;         // 2 warp-cols
    const int mb = wm * 32;          // warp tile: 32 x 64
    const int nb = wn * 64;
    const int lr = lane >> 2;        // 0..7
    const int lc = lane & 3;         // 0..3

    float acc[2][8][4];
    #pragma unroll
    for (int i = 0; i < 2; i++)
        #pragma unroll
        for (int j = 0; j < 8; j++)
            #pragma unroll
            for (int q = 0; q < 4; q++) acc[i][j][q] = 0.f;

    auto load_tile = [&](int buf, int kt) {
        const int k0 = kt * BK;
        #pragma unroll
        for (int it = 0; it < 4; it++) {
            const int c  = tid + it * 256;          // 0..1023
            const int r  = c >> 3;                  // 0..127
            const int kk = (c & 7) << 2;            // 0,4,...,28
            // A tile
            {
                const int gr = (m0 + r < M) ? (m0 + r) : (M - 1);
                const float* g = A + (size_t)gr * K + k0 + kk;
                const uint32_t sa = sAs + (uint32_t)(buf * BM * LDSS + r * LDSS + kk) * 4u;
                cpasync16(sa, g, (m0 + r < M) ? 16 : 0);
            }
            // B tile
            {
                const int gr = (n0 + r < N) ? (n0 + r) : (N - 1);
                const float* g = B + (size_t)gr * K + k0 + kk;
                const uint32_t sb = sBs + (uint32_t)(buf * BN * LDSS + r * LDSS + kk) * 4u;
                cpasync16(sb, g, (n0 + r < N) ? 16 : 0);
            }
        }
    };

    load_tile(0, 0);
    asm volatile("cp.async.commit_group;\n" ::: "memory");

    for (int kt = 0; kt < KT; kt++) {
        if (kt + 1 < KT) load_tile((kt + 1) & 1, kt + 1);
        asm volatile("cp.async.commit_group;\n" ::: "memory");
        asm volatile("cp.async.wait_group 1;\n" ::: "memory");
        __syncthreads();

        const float* Ab = As + (kt & 1) * BM * LDSS;
        const float* Bb = Bs + (kt & 1) * BN * LDSS;

        #pragma unroll
        for (int ks = 0; ks < 4; ks++) {
            const int k = ks * 8;
            uint32_t af[2][4], bf[8][2];
            #pragma unroll
            for (int i = 0; i < 2; i++) {
                const int r = mb + i * 16 + lr;
                af[i][0] = f2tf(Ab[r * LDSS + k + lc]);
                af[i][1] = f2tf(Ab[(r + 8) * LDSS + k + lc]);
                af[i][2] = f2tf(Ab[r * LDSS + k + 4 + lc]);
                af[i][3] = f2tf(Ab[(r + 8) * LDSS + k + 4 + lc]);
            }
            #pragma unroll
            for (int j = 0; j < 8; j++) {
                const int n = nb + j * 8 + lr;
                bf[j][0] = f2tf(Bb[n * LDSS + k + lc]);
                bf[j][1] = f2tf(Bb[n * LDSS + k + 4 + lc]);
            }
            #pragma unroll
            for (int i = 0; i < 2; i++)
                #pragma unroll
                for (int j = 0; j < 8; j++)
                    asm volatile(
                        "mma.sync.aligned.m16n8k8.row.col.f32.tf32.tf32.f32 "
                        "{%0,%1,%2,%3}, {%4,%5,%6,%7}, {%8,%9}, {%0,%1,%2,%3};\n"
                        : "+f"(acc[i][j][0]), "+f"(acc[i][j][1]),
                          "+f"(acc[i][j][2]), "+f"(acc[i][j][3])
                        : "r"(af[i][0]), "r"(af[i][1]), "r"(af[i][2]), "r"(af[i][3]),
                          "r"(bf[j][0]), "r"(bf[j][1]));
        }
        __syncthreads();
    }

    // Epilogue: C[row][col] = acc (+ bias[row]); M is always a multiple of 128 here.
    #pragma unroll
    for (int i = 0; i < 2; i++) {
        const int row0 = m0 + mb + i * 16 + lr;
        const int row1 = row0 + 8;
        const float sv0 = bias ? bias[row0] : 0.f;
        const float sv1 = bias ? bias[row1] : 0.f;
        #pragma unroll
        for (int j = 0; j < 8; j++) {
            const int col = n0 + nb + j * 8 + 2 * lc;
            if (col < N) {   // N is even, col is even -> col+1 also valid
                float2 v0 = make_float2(acc[i][j][0] + sv0, acc[i][j][1] + sv0);
                float2 v1 = make_float2(acc[i][j][2] + sv1, acc[i][j][3] + sv1);
                *reinterpret_cast<float2*>(C + (size_t)row0 * N + col) = v0;
                *reinterpret_cast<float2*>(C + (size_t)row1 * N + col) = v1;
            }
        }
    }
}

// ---------------------------------------------------------------------------
// kernel_launch
// inputs: [0] answer_embed (L,B,T,D) f32  [1] vocab_embed (V,D) f32
//         [2] W (D,D) f32                 [3] b (D,) f32
// out: (L,B,T,V) f32
// out = (A@W) @ E^T + (A@b)
// ---------------------------------------------------------------------------
extern "C" void kernel_launch(void* const* d_in, const int* in_sizes, int n_in,
                              void* d_out, int out_size) {
    const float* A = (const float*)d_in[0];
    const float* E = (const float*)d_in[1];
    const float* W = (const float*)d_in[2];
    const float* b = (const float*)d_in[3];
    float* out = (float*)d_out;

    float *Wt, *Ap, *s;
    cudaGetSymbolAddress((void**)&Wt, g_Wt);
    cudaGetSymbolAddress((void**)&Ap, g_Ap);
    cudaGetSymbolAddress((void**)&s, g_s);

    const int smem_bytes = (2 * BM * LDSS + 2 * BN * LDSS) * 4;  // 73728
    cudaFuncSetAttribute(gemm_tf32_k, cudaFuncAttributeMaxDynamicSharedMemorySize,
                         smem_bytes);

    // 1) Wt = W^T
    transpose_k<<<dim3(24, 24), dim3(32, 8)>>>(W, Wt);
    // 2) s = A @ b
    rowdot_k<<<M_DIM / 8, 256>>>(A, b, s);
    // 3) A' = A @ W  (== A (x) Wt with our [N,K] B layout)
    gemm_tf32_k<<<dim3(M_DIM / BM, D_DIM / BN), 256, smem_bytes>>>(
        A, Wt, Ap, nullptr, M_DIM, D_DIM, D_DIM);
    // 4) out = A' @ E^T + s   (grid.x = m fastest: 5 m-tiles share each E tile in L2)
    gemm_tf32_k<<<dim3(M_DIM / BM, (V_DIM + BN - 1) / BN), 256, smem_bytes>>>(
        Ap, E, out, s, M_DIM, V_DIM, D_DIM);
}

// round 7
// speedup vs baseline: 1.2056x; 1.2056x over previous
#include <cuda_runtime.h>
#include <cstdint>

// Problem constants
#define D_DIM 768
#define M_DIM 640      // L*B*T
#define V_DIM 30000

// Scratch (no allocation allowed -> __device__ globals)
__device__ float g_Wt[D_DIM * D_DIM];   // rna(W^T)
__device__ float g_Ar[M_DIM * D_DIM];   // rna(A)
__device__ float g_Ap[M_DIM * D_DIM];   // rna(A @ W)
__device__ float g_s[M_DIM];            // A @ b

__device__ __forceinline__ uint32_t f2tf(float f) {
    uint32_t r;
    asm("cvt.rna.tf32.f32 %0, %1;" : "=r"(r) : "f"(f));
    return r;
}

// ---------------------------------------------------------------------------
// Prep kernels
// ---------------------------------------------------------------------------
__global__ void transpose_rna_k(const float* __restrict__ W, float* __restrict__ Wt) {
    __shared__ float t[32][33];
    const int bx = blockIdx.x * 32, by = blockIdx.y * 32;
    const int x = threadIdx.x;
    #pragma unroll
    for (int j = threadIdx.y; j < 32; j += 8)
        t[j][x] = W[(by + j) * D_DIM + bx + x];
    __syncthreads();
    #pragma unroll
    for (int j = threadIdx.y; j < 32; j += 8)
        Wt[(bx + j) * D_DIM + by + x] = __uint_as_float(f2tf(t[x][j]));
}

__global__ void round_k(const float* __restrict__ A, float* __restrict__ Ar, int n) {
    int i = blockIdx.x * 256 + threadIdx.x;
    if (i < n) Ar[i] = __uint_as_float(f2tf(A[i]));
}

__global__ void rowdot_k(const float* __restrict__ A, const float* __restrict__ b,
                         float* __restrict__ s) {
    const int m = blockIdx.x * 8 + (threadIdx.x >> 5);
    const int lane = threadIdx.x & 31;
    float acc = 0.f;
    #pragma unroll
    for (int d = lane; d < D_DIM; d += 32) acc += A[m * D_DIM + d] * b[d];
    #pragma unroll
    for (int o = 16; o; o >>= 1) acc += __shfl_xor_sync(0xffffffffu, acc, o);
    if (lane == 0) s[m] = acc;
}

// ---------------------------------------------------------------------------
// GEMM: C[m][n] = sum_k A[m][k]*B[n][k] (+bias[m]); optional tf32-rna output.
// A row-major [M,K], B row-major [N,K]. tf32 mma.sync m16n8k8.
// No in-loop cvt (A pre-rounded; B truncated by HW). LDS.64 fragment loads via
// k-slot relabeling: mma slot lc <- smem col 2*lc, slot lc+4 <- col 2*lc+1.
// ---------------------------------------------------------------------------
#define BM 128
#define BN 128
#define BK 32
#define LDSS 40   // floats per smem row: (LDSS/2) mod 16 == 4 -> LDS.64 conflict-free

__device__ __forceinline__ void cpasync16(uint32_t saddr, const void* g) {
    asm volatile("cp.async.cg.shared.global [%0], [%1], 16;\n"
                 :: "r"(saddr), "l"(g) : "memory");
}

__global__ __launch_bounds__(256, 2) void gemm_tf32_k(
    const float* __restrict__ A, const float* __restrict__ B,
    float* __restrict__ C, const float* __restrict__ bias,
    int M, int N, int K, int rna_out)
{
    extern __shared__ float smem[];
    float* As = smem;                       // [2][BM*LDSS]
    float* Bs = smem + 2 * BM * LDSS;       // [2][BN*LDSS]

    const int tid = threadIdx.x;
    const int m0 = blockIdx.x * BM;
    const int n0 = blockIdx.y * BN;
    const int KT = K / BK;

    const uint32_t sAs = (uint32_t)__cvta_generic_to_shared(As);
    const uint32_t sBs = (uint32_t)__cvta_generic_to_shared(Bs);

    const int lane = tid & 31;
    const int wid  = tid >> 5;
    const int wm = wid & 3;          // 4 warp-rows
    const int wn = wid >> 2;         // 2 warp-cols
    const int mb = wm * 32;          // warp tile 32 x 64
    const int nb = wn * 64;
    const int lr = lane >> 2;        // 0..7
    const int lc = lane & 3;         // 0..3

    float acc[2][8][4];
    #pragma unroll
    for (int i = 0; i < 2; i++)
        #pragma unroll
        for (int j = 0; j < 8; j++)
            #pragma unroll
            for (int q = 0; q < 4; q++) acc[i][j][q] = 0.f;

    auto load_tile = [&](int buf, int kt) {
        const int k0 = kt * BK;
        #pragma unroll
        for (int it = 0; it < 4; it++) {
            const int c  = tid + it * 256;          // 0..1023
            const int r  = c >> 3;                  // 0..127
            const int kk = (c & 7) << 2;            // 0,4,...,28
            {   // A tile (M always a multiple of BM here)
                const float* g = A + (size_t)(m0 + r) * K + k0 + kk;
                cpasync16(sAs + (uint32_t)(buf * BM * LDSS + r * LDSS + kk) * 4u, g);
            }
            {   // B tile (clamp tail rows)
                int gr = n0 + r; if (gr >= N) gr = N - 1;
                const float* g = B + (size_t)gr * K + k0 + kk;
                cpasync16(sBs + (uint32_t)(buf * BN * LDSS + r * LDSS + kk) * 4u, g);
            }
        }
    };

    load_tile(0, 0);
    asm volatile("cp.async.commit_group;\n" ::: "memory");

    for (int kt = 0; kt < KT; kt++) {
        if (kt + 1 < KT) load_tile((kt + 1) & 1, kt + 1);
        asm volatile("cp.async.commit_group;\n" ::: "memory");
        asm volatile("cp.async.wait_group 1;\n" ::: "memory");
        __syncthreads();

        const float* Ab = As + (kt & 1) * BM * LDSS;
        const float* Bb = Bs + (kt & 1) * BN * LDSS;

        #pragma unroll
        for (int ks = 0; ks < 4; ks++) {
            const int kcol = ks * 8 + 2 * lc;   // adjacent pair = slots (lc, lc+4)
            uint32_t af[2][4], bf[8][2];
            #pragma unroll
            for (int i = 0; i < 2; i++) {
                const int r = mb + i * 16 + lr;
                const float2 v0 = *reinterpret_cast<const float2*>(&Ab[r * LDSS + kcol]);
                const float2 v1 = *reinterpret_cast<const float2*>(&Ab[(r + 8) * LDSS + kcol]);
                af[i][0] = __float_as_uint(v0.x);   // slot lc
                af[i][1] = __float_as_uint(v1.x);
                af[i][2] = __float_as_uint(v0.y);   // slot lc+4
                af[i][3] = __float_as_uint(v1.y);
            }
            #pragma unroll
            for (int j = 0; j < 8; j++) {
                const int n = nb + j * 8 + lr;
                const float2 v = *reinterpret_cast<const float2*>(&Bb[n * LDSS + kcol]);
                bf[j][0] = __float_as_uint(v.x);
                bf[j][1] = __float_as_uint(v.y);
            }
            #pragma unroll
            for (int i = 0; i < 2; i++)
                #pragma unroll
                for (int j = 0; j < 8; j++)
                    asm volatile(
                        "mma.sync.aligned.m16n8k8.row.col.f32.tf32.tf32.f32 "
                        "{%0,%1,%2,%3}, {%4,%5,%6,%7}, {%8,%9}, {%0,%1,%2,%3};\n"
                        : "+f"(acc[i][j][0]), "+f"(acc[i][j][1]),
                          "+f"(acc[i][j][2]), "+f"(acc[i][j][3])
                        : "r"(af[i][0]), "r"(af[i][1]), "r"(af[i][2]), "r"(af[i][3]),
                          "r"(bf[j][0]), "r"(bf[j][1]));
        }
        __syncthreads();
    }

    // Epilogue
    #pragma unroll
    for (int i = 0; i < 2; i++) {
        const int row0 = m0 + mb + i * 16 + lr;
        const int row1 = row0 + 8;
        const float sv0 = bias ? bias[row0] : 0.f;
        const float sv1 = bias ? bias[row1] : 0.f;
        #pragma unroll
        for (int j = 0; j < 8; j++) {
            const int col = n0 + nb + j * 8 + 2 * lc;
            if (col < N) {   // N even, col even -> col+1 also valid
                float2 v0 = make_float2(acc[i][j][0] + sv0, acc[i][j][1] + sv0);
                float2 v1 = make_float2(acc[i][j][2] + sv1, acc[i][j][3] + sv1);
                if (rna_out) {
                    v0.x = __uint_as_float(f2tf(v0.x)); v0.y = __uint_as_float(f2tf(v0.y));
                    v1.x = __uint_as_float(f2tf(v1.x)); v1.y = __uint_as_float(f2tf(v1.y));
                }
                *reinterpret_cast<float2*>(C + (size_t)row0 * N + col) = v0;
                *reinterpret_cast<float2*>(C + (size_t)row1 * N + col) = v1;
            }
        }
    }
}

// ---------------------------------------------------------------------------
// out = (A@W) @ E^T + (A@b)
// inputs: [0] answer_embed (L,B,T,D) f32  [1] vocab_embed (V,D) f32
//         [2] W (D,D) f32                 [3] b (D,) f32
// ---------------------------------------------------------------------------
extern "C" void kernel_launch(void* const* d_in, const int* in_sizes, int n_in,
                              void* d_out, int out_size) {
    const float* A = (const float*)d_in[0];
    const float* E = (const float*)d_in[1];
    const float* W = (const float*)d_in[2];
    const float* b = (const float*)d_in[3];
    float* out = (float*)d_out;

    float *Wt, *Ar, *Ap, *s;
    cudaGetSymbolAddress((void**)&Wt, g_Wt);
    cudaGetSymbolAddress((void**)&Ar, g_Ar);
    cudaGetSymbolAddress((void**)&Ap, g_Ap);
    cudaGetSymbolAddress((void**)&s, g_s);

    const int smem_bytes = (2 * BM * LDSS + 2 * BN * LDSS) * 4;  // 81920
    cudaFuncSetAttribute(gemm_tf32_k, cudaFuncAttributeMaxDynamicSharedMemorySize,
                         smem_bytes);

    // Prep: Wt = rna(W^T), Ar = rna(A), s = A@b   (E stays raw: HW truncation)
    transpose_rna_k<<<dim3(24, 24), dim3(32, 8)>>>(W, Wt);
    round_k<<<(M_DIM * D_DIM) / 256, 256>>>(A, Ar, M_DIM * D_DIM);
    rowdot_k<<<M_DIM / 8, 256>>>(A, b, s);

    // 1) A' = rna(A @ W)
    gemm_tf32_k<<<dim3(M_DIM / BM, D_DIM / BN), 256, smem_bytes>>>(
        Ar, Wt, Ap, nullptr, M_DIM, D_DIM, D_DIM, 1);
    // 2) out = A' @ E^T + s   (x-fastest grid: 5 m-tiles share each E tile in L2)
    gemm_tf32_k<<<dim3(M_DIM / BM, (V_DIM + BN - 1) / BN), 256, smem_bytes>>>(
        Ap, E, out, s, M_DIM, V_DIM, D_DIM, 0);
}

// round 8
// speedup vs baseline: 1.8723x; 1.5530x over previous
#include <cuda_runtime.h>
#include <cuda_fp16.h>
#include <cstdint>

// Problem constants
#define D_DIM 768
#define M_DIM 640      // L*B*T
#define V_DIM 30000

// Scratch (no allocation allowed -> __device__ globals)
__device__ float  g_Wt[D_DIM * D_DIM];        // rna(W^T), tf32-rounded fp32
__device__ float  g_Ar[M_DIM * D_DIM];        // rna(A)
__device__ __half g_Aph[M_DIM * D_DIM];       // fp16(A @ W)
__device__ __half g_Eh[V_DIM * D_DIM];        // fp16(E)
__device__ float  g_s[M_DIM];                 // A @ b

__device__ __forceinline__ uint32_t f2tf(float f) {
    uint32_t r;
    asm("cvt.rna.tf32.f32 %0, %1;" : "=r"(r) : "f"(f));
    return r;
}
__device__ __forceinline__ void cpasync16(uint32_t saddr, const void* g) {
    asm volatile("cp.async.cg.shared.global [%0], [%1], 16;\n"
                 :: "r"(saddr), "l"(g) : "memory");
}
#define CP_COMMIT() asm volatile("cp.async.commit_group;\n" ::: "memory")
#define CP_WAIT1()  asm volatile("cp.async.wait_group 1;\n" ::: "memory")

// ---------------------------------------------------------------------------
// Prep kernels
// ---------------------------------------------------------------------------
__global__ void transpose_rna_k(const float* __restrict__ W, float* __restrict__ Wt) {
    __shared__ float t[32][33];
    const int bx = blockIdx.x * 32, by = blockIdx.y * 32;
    const int x = threadIdx.x;
    #pragma unroll
    for (int j = threadIdx.y; j < 32; j += 8)
        t[j][x] = W[(by + j) * D_DIM + bx + x];
    __syncthreads();
    #pragma unroll
    for (int j = threadIdx.y; j < 32; j += 8)
        Wt[(bx + j) * D_DIM + by + x] = __uint_as_float(f2tf(t[x][j]));
}

__global__ void round_k(const float* __restrict__ A, float* __restrict__ Ar, int n) {
    int i = blockIdx.x * 256 + threadIdx.x;
    if (i < n) Ar[i] = __uint_as_float(f2tf(A[i]));
}

// E (fp32) -> Eh (fp16), 8 elems/thread
__global__ void convE_k(const float* __restrict__ E, __half* __restrict__ Eh, int n8) {
    int i = blockIdx.x * 256 + threadIdx.x;
    if (i < n8) {
        const float4* p = reinterpret_cast<const float4*>(E) + (size_t)i * 2;
        float4 x = p[0], y = p[1];
        __half2 h0 = __floats2half2_rn(x.x, x.y);
        __half2 h1 = __floats2half2_rn(x.z, x.w);
        __half2 h2 = __floats2half2_rn(y.x, y.y);
        __half2 h3 = __floats2half2_rn(y.z, y.w);
        uint4 o;
        o.x = *reinterpret_cast<uint32_t*>(&h0);
        o.y = *reinterpret_cast<uint32_t*>(&h1);
        o.z = *reinterpret_cast<uint32_t*>(&h2);
        o.w = *reinterpret_cast<uint32_t*>(&h3);
        reinterpret_cast<uint4*>(Eh)[i] = o;
    }
}

__global__ void rowdot_k(const float* __restrict__ A, const float* __restrict__ b,
                         float* __restrict__ s) {
    const int m = blockIdx.x * 8 + (threadIdx.x >> 5);
    const int lane = threadIdx.x & 31;
    float acc = 0.f;
    #pragma unroll
    for (int d = lane; d < D_DIM; d += 32) acc += A[m * D_DIM + d] * b[d];
    #pragma unroll
    for (int o = 16; o; o >>= 1) acc += __shfl_xor_sync(0xffffffffu, acc, o);
    if (lane == 0) s[m] = acc;
}

// ---------------------------------------------------------------------------
// GEMM1 (tf32): A'h[m][n] = fp16( sum_k Ar[m][k] * Wt[n][k] )
// 64x64 tiles (120 CTAs), m16n8k8 tf32, LDS.64 k-slot relabel.
// ---------------------------------------------------------------------------
#define BM1 64
#define BN1 64
#define BK1 32
#define LDS1 40

__global__ __launch_bounds__(256, 2) void gemm1_tf32_k(
    const float* __restrict__ A, const float* __restrict__ B, __half* __restrict__ C)
{
    extern __shared__ float smem[];
    float* As = smem;                        // [2][BM1*LDS1]
    float* Bs = smem + 2 * BM1 * LDS1;       // [2][BN1*LDS1]

    const int tid = threadIdx.x;
    const int m0 = blockIdx.x * BM1;
    const int n0 = blockIdx.y * BN1;
    const int KT = D_DIM / BK1;              // 24

    const uint32_t sAs = (uint32_t)__cvta_generic_to_shared(As);
    const uint32_t sBs = (uint32_t)__cvta_generic_to_shared(Bs);

    const int lane = tid & 31;
    const int wid  = tid >> 5;
    const int wm = wid & 3;                  // 4 warp-rows x 16
    const int wn = wid >> 2;                 // 2 warp-cols x 32
    const int mb = wm * 16;
    const int nb = wn * 32;
    const int lr = lane >> 2;
    const int lc = lane & 3;

    float acc[4][4];
    #pragma unroll
    for (int j = 0; j < 4; j++)
        #pragma unroll
        for (int q = 0; q < 4; q++) acc[j][q] = 0.f;

    auto load_tile = [&](int buf, int kt) {
        const int k0 = kt * BK1;
        #pragma unroll
        for (int it = 0; it < 2; it++) {
            const int c  = tid + it * 256;   // 0..511
            const int r  = c >> 3;           // 0..63
            const int kk = (c & 7) << 2;
            cpasync16(sAs + (uint32_t)(buf * BM1 * LDS1 + r * LDS1 + kk) * 4u,
                      A + (size_t)(m0 + r) * D_DIM + k0 + kk);
            cpasync16(sBs + (uint32_t)(buf * BN1 * LDS1 + r * LDS1 + kk) * 4u,
                      B + (size_t)(n0 + r) * D_DIM + k0 + kk);
        }
    };

    load_tile(0, 0);
    CP_COMMIT();

    for (int kt = 0; kt < KT; kt++) {
        if (kt + 1 < KT) load_tile((kt + 1) & 1, kt + 1);
        CP_COMMIT();
        CP_WAIT1();
        __syncthreads();

        const float* Ab = As + (kt & 1) * BM1 * LDS1;
        const float* Bb = Bs + (kt & 1) * BN1 * LDS1;

        #pragma unroll
        for (int ks = 0; ks < 4; ks++) {
            const int kcol = ks * 8 + 2 * lc;
            uint32_t af[4], bf[4][2];
            {
                const int r = mb + lr;
                const float2 v0 = *reinterpret_cast<const float2*>(&Ab[r * LDS1 + kcol]);
                const float2 v1 = *reinterpret_cast<const float2*>(&Ab[(r + 8) * LDS1 + kcol]);
                af[0] = __float_as_uint(v0.x);
                af[1] = __float_as_uint(v1.x);
                af[2] = __float_as_uint(v0.y);
                af[3] = __float_as_uint(v1.y);
            }
            #pragma unroll
            for (int j = 0; j < 4; j++) {
                const int n = nb + j * 8 + lr;
                const float2 v = *reinterpret_cast<const float2*>(&Bb[n * LDS1 + kcol]);
                bf[j][0] = __float_as_uint(v.x);
                bf[j][1] = __float_as_uint(v.y);
            }
            #pragma unroll
            for (int j = 0; j < 4; j++)
                asm volatile(
                    "mma.sync.aligned.m16n8k8.row.col.f32.tf32.tf32.f32 "
                    "{%0,%1,%2,%3}, {%4,%5,%6,%7}, {%8,%9}, {%0,%1,%2,%3};\n"
                    : "+f"(acc[j][0]), "+f"(acc[j][1]), "+f"(acc[j][2]), "+f"(acc[j][3])
                    : "r"(af[0]), "r"(af[1]), "r"(af[2]), "r"(af[3]),
                      "r"(bf[j][0]), "r"(bf[j][1]));
        }
        __syncthreads();
    }

    // Epilogue: fp16 output
    const int row0 = m0 + mb + lr;
    const int row1 = row0 + 8;
    #pragma unroll
    for (int j = 0; j < 4; j++) {
        const int col = n0 + nb + j * 8 + 2 * lc;
        __half2 h0 = __floats2half2_rn(acc[j][0], acc[j][1]);
        __half2 h1 = __floats2half2_rn(acc[j][2], acc[j][3]);
        *reinterpret_cast<__half2*>(C + (size_t)row0 * D_DIM + col) = h0;
        *reinterpret_cast<__half2*>(C + (size_t)row1 * D_DIM + col) = h1;
    }
}

// ---------------------------------------------------------------------------
// GEMM2 (fp16): out[m][n] = sum_k Ah[m][k]*Bh[n][k] + bias[m]
// 128x128 tiles, BK=64 halves, m16n8k16 fp16 mma, fp32 accum.
// k-slot relabel: logical slots {2lc,2lc+1,2lc+8,2lc+9} <- phys cols {4lc..4lc+3}
// -> every fragment is one 8-byte LDS. Row stride 160B: addr/8 mod 16 = 4lr+lc
// distinct per LDS.64 phase -> conflict-free.
// ---------------------------------------------------------------------------
#define BM2 128
#define BN2 128
#define BK2 64      // halves per k-tile (128 B)
#define S2H 80      // smem row stride in halves (160 B)

__global__ __launch_bounds__(256, 2) void gemm2_fp16_k(
    const __half* __restrict__ A, const __half* __restrict__ B,
    float* __restrict__ C, const float* __restrict__ bias, int N)
{
    extern __shared__ __half smh[];
    __half* As = smh;                        // [2][BM2*S2H]
    __half* Bs = smh + 2 * BM2 * S2H;        // [2][BN2*S2H]

    const int tid = threadIdx.x;
    const int m0 = blockIdx.x * BM2;
    const int n0 = blockIdx.y * BN2;
    const int KT = D_DIM / BK2;              // 12

    const uint32_t sAs = (uint32_t)__cvta_generic_to_shared(As);
    const uint32_t sBs = (uint32_t)__cvta_generic_to_shared(Bs);

    const int lane = tid & 31;
    const int wid  = tid >> 5;
    const int wm = wid & 3;                  // 4 warp-rows x 32
    const int wn = wid >> 2;                 // 2 warp-cols x 64
    const int mb = wm * 32;
    const int nb = wn * 64;
    const int lr = lane >> 2;
    const int lc = lane & 3;

    float acc[2][8][4];
    #pragma unroll
    for (int i = 0; i < 2; i++)
        #pragma unroll
        for (int j = 0; j < 8; j++)
            #pragma unroll
            for (int q = 0; q < 4; q++) acc[i][j][q] = 0.f;

    auto load_tile = [&](int buf, int kt) {
        const int k0 = kt * BK2;
        #pragma unroll
        for (int it = 0; it < 4; it++) {
            const int c  = tid + it * 256;   // 0..1023
            const int r  = c >> 3;           // 0..127
            const int cc = c & 7;            // 16B chunk within 128B row
            cpasync16(sAs + (uint32_t)((buf * BM2 + r) * S2H * 2 + cc * 16),
                      A + (size_t)(m0 + r) * D_DIM + k0 + cc * 8);
            int gr = n0 + r; if (gr >= N) gr = N - 1;
            cpasync16(sBs + (uint32_t)((buf * BN2 + r) * S2H * 2 + cc * 16),
                      B + (size_t)gr * D_DIM + k0 + cc * 8);
        }
    };

    load_tile(0, 0);
    CP_COMMIT();

    for (int kt = 0; kt < KT; kt++) {
        if (kt + 1 < KT) load_tile((kt + 1) & 1, kt + 1);
        CP_COMMIT();
        CP_WAIT1();
        __syncthreads();

        const __half* Ab = As + (kt & 1) * BM2 * S2H;
        const __half* Bb = Bs + (kt & 1) * BN2 * S2H;

        #pragma unroll
        for (int ks = 0; ks < 4; ks++) {
            const int kcol = ks * 16 + 4 * lc;      // halves
            uint32_t af[2][4], bf[8][2];
            #pragma unroll
            for (int i = 0; i < 2; i++) {
                const int r = mb + i * 16 + lr;
                const uint2 vlo = *reinterpret_cast<const uint2*>(&Ab[r * S2H + kcol]);
                const uint2 vhi = *reinterpret_cast<const uint2*>(&Ab[(r + 8) * S2H + kcol]);
                af[i][0] = vlo.x;    // row lr,   slots 2lc,2lc+1
                af[i][1] = vhi.x;    // row lr+8, slots 2lc,2lc+1
                af[i][2] = vlo.y;    // row lr,   slots 2lc+8,2lc+9
                af[i][3] = vhi.y;    // row lr+8, slots 2lc+8,2lc+9
            }
            #pragma unroll
            for (int j = 0; j < 8; j++) {
                const int n = nb + j * 8 + lr;
                const uint2 v = *reinterpret_cast<const uint2*>(&Bb[n * S2H + kcol]);
                bf[j][0] = v.x;
                bf[j][1] = v.y;
            }
            #pragma unroll
            for (int i = 0; i < 2; i++)
                #pragma unroll
                for (int j = 0; j < 8; j++)
                    asm volatile(
                        "mma.sync.aligned.m16n8k16.row.col.f32.f16.f16.f32 "
                        "{%0,%1,%2,%3}, {%4,%5,%6,%7}, {%8,%9}, {%0,%1,%2,%3};\n"
                        : "+f"(acc[i][j][0]), "+f"(acc[i][j][1]),
                          "+f"(acc[i][j][2]), "+f"(acc[i][j][3])
                        : "r"(af[i][0]), "r"(af[i][1]), "r"(af[i][2]), "r"(af[i][3]),
                          "r"(bf[j][0]), "r"(bf[j][1]));
        }
        __syncthreads();
    }

    // Epilogue
    #pragma unroll
    for (int i = 0; i < 2; i++) {
        const int row0 = m0 + mb + i * 16 + lr;
        const int row1 = row0 + 8;
        const float sv0 = bias[row0];
        const float sv1 = bias[row1];
        #pragma unroll
        for (int j = 0; j < 8; j++) {
            const int col = n0 + nb + j * 8 + 2 * lc;
            if (col < N) {   // N even, col even -> col+1 valid
                float2 v0 = make_float2(acc[i][j][0] + sv0, acc[i][j][1] + sv0);
                float2 v1 = make_float2(acc[i][j][2] + sv1, acc[i][j][3] + sv1);
                *reinterpret_cast<float2*>(C + (size_t)row0 * N + col) = v0;
                *reinterpret_cast<float2*>(C + (size_t)row1 * N + col) = v1;
            }
        }
    }
}

// ---------------------------------------------------------------------------
// out = (A@W) @ E^T + (A@b)
// inputs: [0] answer_embed (L,B,T,D) f32  [1] vocab_embed (V,D) f32
//         [2] W (D,D) f32                 [3] b (D,) f32
// ---------------------------------------------------------------------------
extern "C" void kernel_launch(void* const* d_in, const int* in_sizes, int n_in,
                              void* d_out, int out_size) {
    const float* A = (const float*)d_in[0];
    const float* E = (const float*)d_in[1];
    const float* W = (const float*)d_in[2];
    const float* b = (const float*)d_in[3];
    float* out = (float*)d_out;

    float *Wt, *Ar, *s;
    __half *Aph, *Eh;
    cudaGetSymbolAddress((void**)&Wt, g_Wt);
    cudaGetSymbolAddress((void**)&Ar, g_Ar);
    cudaGetSymbolAddress((void**)&s, g_s);
    cudaGetSymbolAddress((void**)&Aph, g_Aph);
    cudaGetSymbolAddress((void**)&Eh, g_Eh);

    const int smem1 = (2 * BM1 * LDS1 + 2 * BN1 * LDS1) * 4;        // 40960
    const int smem2 = (2 * BM2 * S2H + 2 * BN2 * S2H) * 2;          // 81920
    cudaFuncSetAttribute(gemm1_tf32_k, cudaFuncAttributeMaxDynamicSharedMemorySize, smem1);
    cudaFuncSetAttribute(gemm2_fp16_k, cudaFuncAttributeMaxDynamicSharedMemorySize, smem2);

    // Prep
    convE_k<<<(V_DIM * D_DIM / 8 + 255) / 256, 256>>>(E, Eh, V_DIM * D_DIM / 8);
    transpose_rna_k<<<dim3(24, 24), dim3(32, 8)>>>(W, Wt);
    round_k<<<(M_DIM * D_DIM) / 256, 256>>>(A, Ar, M_DIM * D_DIM);
    rowdot_k<<<M_DIM / 8, 256>>>(A, b, s);

    // 1) A'h = fp16(A @ W)
    gemm1_tf32_k<<<dim3(M_DIM / BM1, D_DIM / BN1), 256, smem1>>>(Ar, Wt, Aph);
    // 2) out = A'h @ Eh^T + s   (x-fastest grid: 5 m-tiles share E tiles in L2)
    gemm2_fp16_k<<<dim3(M_DIM / BM2, (V_DIM + BN2 - 1) / BN2), 256, smem2>>>(
        Aph, Eh, out, s, V_DIM);
}

// round 9
// speedup vs baseline: 2.0950x; 1.1189x over previous
#include <cuda_runtime.h>
#include <cuda_fp16.h>
#include <cstdint>

// Problem constants
#define D_DIM 768
#define M_DIM 640      // L*B*T
#define V_DIM 30000

// Scratch (no allocation allowed -> __device__ globals)
__device__ float  g_Wt[D_DIM * D_DIM];        // rna(W^T)
__device__ float  g_Ar[M_DIM * D_DIM];        // rna(A)
__device__ __half g_Aph[M_DIM * D_DIM];       // fp16(A @ W)
__device__ __half g_Eh[V_DIM * D_DIM];        // fp16(E)
__device__ float  g_s[M_DIM];                 // A @ b

__device__ __forceinline__ uint32_t f2tf(float f) {
    uint32_t r;
    asm("cvt.rna.tf32.f32 %0, %1;" : "=r"(r) : "f"(f));
    return r;
}
__device__ __forceinline__ void cpasync16(uint32_t saddr, const void* g) {
    asm volatile("cp.async.cg.shared.global [%0], [%1], 16;\n"
                 :: "r"(saddr), "l"(g) : "memory");
}
#define CP_COMMIT() asm volatile("cp.async.commit_group;\n" ::: "memory")
#define CP_WAIT1()  asm volatile("cp.async.wait_group 1;\n" ::: "memory")

__device__ __forceinline__ void ldsm4(uint32_t& r0, uint32_t& r1, uint32_t& r2,
                                      uint32_t& r3, uint32_t addr) {
    asm volatile("ldmatrix.sync.aligned.m8n8.x4.shared.b16 {%0,%1,%2,%3}, [%4];"
                 : "=r"(r0), "=r"(r1), "=r"(r2), "=r"(r3) : "r"(addr));
}

// ---------------------------------------------------------------------------
// Prep kernels
// ---------------------------------------------------------------------------
__global__ void transpose_rna_k(const float* __restrict__ W, float* __restrict__ Wt) {
    __shared__ float t[32][33];
    const int bx = blockIdx.x * 32, by = blockIdx.y * 32;
    const int x = threadIdx.x;
    #pragma unroll
    for (int j = threadIdx.y; j < 32; j += 8)
        t[j][x] = W[(by + j) * D_DIM + bx + x];
    __syncthreads();
    #pragma unroll
    for (int j = threadIdx.y; j < 32; j += 8)
        Wt[(bx + j) * D_DIM + by + x] = __uint_as_float(f2tf(t[x][j]));
}

// Fused: Ar = rna(A) and s = A @ b. One block per row m.
__global__ void roundrow_k(const float* __restrict__ A, const float* __restrict__ b,
                           float* __restrict__ Ar, float* __restrict__ s) {
    __shared__ float red[8];
    const int m = blockIdx.x;
    const int tid = threadIdx.x;
    float acc = 0.f;
    #pragma unroll
    for (int d = tid; d < D_DIM; d += 256) {
        const float a = A[(size_t)m * D_DIM + d];
        Ar[(size_t)m * D_DIM + d] = __uint_as_float(f2tf(a));
        acc += a * b[d];
    }
    #pragma unroll
    for (int o = 16; o; o >>= 1) acc += __shfl_xor_sync(0xffffffffu, acc, o);
    if ((tid & 31) == 0) red[tid >> 5] = acc;
    __syncthreads();
    if (tid < 8) {
        float v = red[tid];
        #pragma unroll
        for (int o = 4; o; o >>= 1) v += __shfl_xor_sync(0xffu, v, o);
        if (tid == 0) s[m] = v;
    }
}

// E (fp32) -> Eh (fp16), 8 elems/thread
__global__ void convE_k(const float* __restrict__ E, __half* __restrict__ Eh, int n8) {
    int i = blockIdx.x * 256 + threadIdx.x;
    if (i < n8) {
        const float4* p = reinterpret_cast<const float4*>(E) + (size_t)i * 2;
        float4 x = p[0], y = p[1];
        __half2 h0 = __floats2half2_rn(x.x, x.y);
        __half2 h1 = __floats2half2_rn(x.z, x.w);
        __half2 h2 = __floats2half2_rn(y.x, y.y);
        __half2 h3 = __floats2half2_rn(y.z, y.w);
        uint4 o;
        o.x = *reinterpret_cast<uint32_t*>(&h0);
        o.y = *reinterpret_cast<uint32_t*>(&h1);
        o.z = *reinterpret_cast<uint32_t*>(&h2);
        o.w = *reinterpret_cast<uint32_t*>(&h3);
        reinterpret_cast<uint4*>(Eh)[i] = o;
    }
}

// ---------------------------------------------------------------------------
// GEMM1 (tf32): A'h = fp16(Ar @ Wt^T), 64x64 tiles, m16n8k8, LDS.64 relabel.
// ---------------------------------------------------------------------------
#define BM1 64
#define BN1 64
#define BK1 32
#define LDS1 40

__global__ __launch_bounds__(256, 2) void gemm1_tf32_k(
    const float* __restrict__ A, const float* __restrict__ B, __half* __restrict__ C)
{
    extern __shared__ float smem[];
    float* As = smem;
    float* Bs = smem + 2 * BM1 * LDS1;

    const int tid = threadIdx.x;
    const int m0 = blockIdx.x * BM1;
    const int n0 = blockIdx.y * BN1;
    const int KT = D_DIM / BK1;

    const uint32_t sAs = (uint32_t)__cvta_generic_to_shared(As);
    const uint32_t sBs = (uint32_t)__cvta_generic_to_shared(Bs);

    const int lane = tid & 31;
    const int wid  = tid >> 5;
    const int mb = (wid & 3) * 16;
    const int nb = (wid >> 2) * 32;
    const int lr = lane >> 2;
    const int lc = lane & 3;

    float acc[4][4];
    #pragma unroll
    for (int j = 0; j < 4; j++)
        #pragma unroll
        for (int q = 0; q < 4; q++) acc[j][q] = 0.f;

    auto load_tile = [&](int buf, int kt) {
        const int k0 = kt * BK1;
        #pragma unroll
        for (int it = 0; it < 2; it++) {
            const int c  = tid + it * 256;
            const int r  = c >> 3;
            const int kk = (c & 7) << 2;
            cpasync16(sAs + (uint32_t)(buf * BM1 * LDS1 + r * LDS1 + kk) * 4u,
                      A + (size_t)(m0 + r) * D_DIM + k0 + kk);
            cpasync16(sBs + (uint32_t)(buf * BN1 * LDS1 + r * LDS1 + kk) * 4u,
                      B + (size_t)(n0 + r) * D_DIM + k0 + kk);
        }
    };

    load_tile(0, 0);
    CP_COMMIT();

    for (int kt = 0; kt < KT; kt++) {
        if (kt + 1 < KT) load_tile((kt + 1) & 1, kt + 1);
        CP_COMMIT();
        CP_WAIT1();
        __syncthreads();

        const float* Ab = As + (kt & 1) * BM1 * LDS1;
        const float* Bb = Bs + (kt & 1) * BN1 * LDS1;

        #pragma unroll
        for (int ks = 0; ks < 4; ks++) {
            const int kcol = ks * 8 + 2 * lc;
            uint32_t af[4], bf[4][2];
            {
                const int r = mb + lr;
                const float2 v0 = *reinterpret_cast<const float2*>(&Ab[r * LDS1 + kcol]);
                const float2 v1 = *reinterpret_cast<const float2*>(&Ab[(r + 8) * LDS1 + kcol]);
                af[0] = __float_as_uint(v0.x);
                af[1] = __float_as_uint(v1.x);
                af[2] = __float_as_uint(v0.y);
                af[3] = __float_as_uint(v1.y);
            }
            #pragma unroll
            for (int j = 0; j < 4; j++) {
                const int n = nb + j * 8 + lr;
                const float2 v = *reinterpret_cast<const float2*>(&Bb[n * LDS1 + kcol]);
                bf[j][0] = __float_as_uint(v.x);
                bf[j][1] = __float_as_uint(v.y);
            }
            #pragma unroll
            for (int j = 0; j < 4; j++)
                asm volatile(
                    "mma.sync.aligned.m16n8k8.row.col.f32.tf32.tf32.f32 "
                    "{%0,%1,%2,%3}, {%4,%5,%6,%7}, {%8,%9}, {%0,%1,%2,%3};\n"
                    : "+f"(acc[j][0]), "+f"(acc[j][1]), "+f"(acc[j][2]), "+f"(acc[j][3])
                    : "r"(af[0]), "r"(af[1]), "r"(af[2]), "r"(af[3]),
                      "r"(bf[j][0]), "r"(bf[j][1]));
        }
        __syncthreads();
    }

    const int row0 = m0 + mb + lr;
    const int row1 = row0 + 8;
    #pragma unroll
    for (int j = 0; j < 4; j++) {
        const int col = n0 + nb + j * 8 + 2 * lc;
        *reinterpret_cast<__half2*>(C + (size_t)row0 * D_DIM + col) =
            __floats2half2_rn(acc[j][0], acc[j][1]);
        *reinterpret_cast<__half2*>(C + (size_t)row1 * D_DIM + col) =
            __floats2half2_rn(acc[j][2], acc[j][3]);
    }
}

// ---------------------------------------------------------------------------
// GEMM2 (fp16): out = Ah @ Bh^T + bias. 128x128 tiles, BK=64 halves.
// 3-stage cp.async pipeline; XOR-swizzled 128B rows; ldmatrix.x4 fragments.
// ---------------------------------------------------------------------------
#define BM2 128
#define BN2 128
#define BK2 64
#define NST 3
#define ASTG 16384                       // A stage bytes (128 rows x 128B)
#define STG  32768                       // stage bytes (A+B)

__global__ __launch_bounds__(256, 2) void gemm2_fp16_k(
    const __half* __restrict__ A, const __half* __restrict__ B,
    float* __restrict__ C, const float* __restrict__ bias, int N)
{
    extern __shared__ __half smh[];
    const uint32_t sb = (uint32_t)__cvta_generic_to_shared(smh);

    const int tid = threadIdx.x;
    const int m0 = blockIdx.x * BM2;
    const int n0 = blockIdx.y * BN2;
    const int KT = D_DIM / BK2;          // 12

    const int lane = tid & 31;
    const int wid  = tid >> 5;
    const int mb = (wid & 3) * 32;
    const int nb = (wid >> 2) * 64;
    const int lr = lane >> 2;
    const int lc = lane & 3;

    // ldmatrix lane geometry
    const int lrow = lane & 7;
    const int mat  = lane >> 3;          // 0..3
    // A x4 for i: rows = mb+i*16 + ((mat&1)<<3) + lrow ; chunk = ks*2 + (mat>>1)
    int aoff[2], arm[2];
    #pragma unroll
    for (int i = 0; i < 2; i++) {
        const int r = mb + i * 16 + ((mat & 1) << 3) + lrow;
        aoff[i] = r * 128;
        arm[i] = r & 7;
    }
    const int acb = mat >> 1;
    // B x4 for jp: rows = nb + (jp*2 + (mat>>1))*8 + lrow ; chunk = ks*2 + (mat&1)
    int boff[4], brm[4];
    #pragma unroll
    for (int jp = 0; jp < 4; jp++) {
        const int r = nb + (jp * 2 + (mat >> 1)) * 8 + lrow;
        boff[jp] = r * 128;
        brm[jp] = r & 7;
    }
    const int bcb = mat & 1;

    float acc[2][8][4];
    #pragma unroll
    for (int i = 0; i < 2; i++)
        #pragma unroll
        for (int j = 0; j < 8; j++)
            #pragma unroll
            for (int q = 0; q < 4; q++) acc[i][j][q] = 0.f;

    auto load_tile = [&](int buf, int kt) {
        const int k0 = kt * BK2;
        const uint32_t stg = sb + (uint32_t)buf * STG;
        #pragma unroll
        for (int it = 0; it < 4; it++) {
            const int c  = tid + it * 256;   // 0..1023
            const int r  = c >> 3;
            const int cc = c & 7;
            const uint32_t soff = (uint32_t)(r * 128 + ((cc ^ (r & 7)) << 4));
            cpasync16(stg + soff, A + (size_t)(m0 + r) * D_DIM + k0 + cc * 8);
            int gr = n0 + r; if (gr >= N) gr = N - 1;
            cpasync16(stg + ASTG + soff, B + (size_t)gr * D_DIM + k0 + cc * 8);
        }
    };

    // Prologue: stages 0,1
    load_tile(0, 0); CP_COMMIT();
    load_tile(1, 1); CP_COMMIT();

    for (int kt = 0; kt < KT; kt++) {
        CP_WAIT1();
        __syncthreads();

        const int lt = kt + 2;
        if (lt < KT) load_tile(lt % NST, lt);
        CP_COMMIT();

        const uint32_t Ab = sb + (uint32_t)(kt % NST) * STG;
        const uint32_t Bb = Ab + ASTG;

        #pragma unroll
        for (int ks = 0; ks < 4; ks++) {
            uint32_t aq[2][4], bq[4][4];
            #pragma unroll
            for (int i = 0; i < 2; i++)
                ldsm4(aq[i][0], aq[i][1], aq[i][2], aq[i][3],
                      Ab + aoff[i] + (((ks * 2 + acb) ^ arm[i]) << 4));
            #pragma unroll
            for (int jp = 0; jp < 4; jp++)
                ldsm4(bq[jp][0], bq[jp][1], bq[jp][2], bq[jp][3],
                      Bb + boff[jp] + (((ks * 2 + bcb) ^ brm[jp]) << 4));
            #pragma unroll
            for (int i = 0; i < 2; i++)
                #pragma unroll
                for (int j = 0; j < 8; j++) {
                    const uint32_t b0 = bq[j >> 1][(j & 1) * 2];
                    const uint32_t b1 = bq[j >> 1][(j & 1) * 2 + 1];
                    asm volatile(
                        "mma.sync.aligned.m16n8k16.row.col.f32.f16.f16.f32 "
                        "{%0,%1,%2,%3}, {%4,%5,%6,%7}, {%8,%9}, {%0,%1,%2,%3};\n"
                        : "+f"(acc[i][j][0]), "+f"(acc[i][j][1]),
                          "+f"(acc[i][j][2]), "+f"(acc[i][j][3])
                        : "r"(aq[i][0]), "r"(aq[i][1]), "r"(aq[i][2]), "r"(aq[i][3]),
                          "r"(b0), "r"(b1));
                }
        }
        __syncthreads();
    }

    // Epilogue
    #pragma unroll
    for (int i = 0; i < 2; i++) {
        const int row0 = m0 + mb + i * 16 + lr;
        const int row1 = row0 + 8;
        const float sv0 = bias[row0];
        const float sv1 = bias[row1];
        #pragma unroll
        for (int j = 0; j < 8; j++) {
            const int col = n0 + nb + j * 8 + 2 * lc;
            if (col < N) {
                float2 v0 = make_float2(acc[i][j][0] + sv0, acc[i][j][1] + sv0);
                float2 v1 = make_float2(acc[i][j][2] + sv1, acc[i][j][3] + sv1);
                *reinterpret_cast<float2*>(C + (size_t)row0 * N + col) = v0;
                *reinterpret_cast<float2*>(C + (size_t)row1 * N + col) = v1;
            }
        }
    }
}

// ---------------------------------------------------------------------------
// out = (A@W) @ E^T + (A@b)
// ---------------------------------------------------------------------------
extern "C" void kernel_launch(void* const* d_in, const int* in_sizes, int n_in,
                              void* d_out, int out_size) {
    const float* A = (const float*)d_in[0];
    const float* E = (const float*)d_in[1];
    const float* W = (const float*)d_in[2];
    const float* b = (const float*)d_in[3];
    float* out = (float*)d_out;

    float *Wt, *Ar, *s;
    __half *Aph, *Eh;
    cudaGetSymbolAddress((void**)&Wt, g_Wt);
    cudaGetSymbolAddress((void**)&Ar, g_Ar);
    cudaGetSymbolAddress((void**)&s, g_s);
    cudaGetSymbolAddress((void**)&Aph, g_Aph);
    cudaGetSymbolAddress((void**)&Eh, g_Eh);

    const int smem1 = (2 * BM1 * LDS1 + 2 * BN1 * LDS1) * 4;   // 40960
    const int smem2 = NST * STG;                               // 98304
    cudaFuncSetAttribute(gemm1_tf32_k, cudaFuncAttributeMaxDynamicSharedMemorySize, smem1);
    cudaFuncSetAttribute(gemm2_fp16_k, cudaFuncAttributeMaxDynamicSharedMemorySize, smem2);

    // Prep
    convE_k<<<(V_DIM * D_DIM / 8 + 255) / 256, 256>>>(E, Eh, V_DIM * D_DIM / 8);
    transpose_rna_k<<<dim3(24, 24), dim3(32, 8)>>>(W, Wt);
    roundrow_k<<<M_DIM, 256>>>(A, b, Ar, s);

    // 1) A'h = fp16(A @ W)
    gemm1_tf32_k<<<dim3(M_DIM / BM1, D_DIM / BN1), 256, smem1>>>(Ar, Wt, Aph);
    // 2) out = A'h @ Eh^T + s
    gemm2_fp16_k<<<dim3(M_DIM / BM2, (V_DIM + BN2 - 1) / BN2), 256, smem2>>>(
        Aph, Eh, out, s, V_DIM);
}

// round 10
// speedup vs baseline: 2.1059x; 1.0052x over previous
#include <cuda_runtime.h>
#include <cuda_fp16.h>
#include <cstdint>

// Problem constants
#define D_DIM 768
#define M_DIM 640      // L*B*T
#define V_DIM 30000

// Scratch (no allocation allowed -> __device__ globals)
__device__ float  g_Wt[D_DIM * D_DIM];        // rna(W^T)
__device__ float  g_Ar[M_DIM * D_DIM];        // rna(A)
__device__ __half g_Aph[M_DIM * D_DIM];       // fp16(A @ W)
__device__ __half g_Eh[V_DIM * D_DIM];        // fp16(E)
__device__ float  g_s[M_DIM];                 // A @ b

__device__ __forceinline__ uint32_t f2tf(float f) {
    uint32_t r;
    asm("cvt.rna.tf32.f32 %0, %1;" : "=r"(r) : "f"(f));
    return r;
}
__device__ __forceinline__ void cpasync16(uint32_t saddr, const void* g) {
    asm volatile("cp.async.cg.shared.global [%0], [%1], 16;\n"
                 :: "r"(saddr), "l"(g) : "memory");
}
#define CP_COMMIT() asm volatile("cp.async.commit_group;\n" ::: "memory")
#define CP_WAIT1()  asm volatile("cp.async.wait_group 1;\n" ::: "memory")
#define CP_WAIT2()  asm volatile("cp.async.wait_group 2;\n" ::: "memory")

__device__ __forceinline__ void ldsm4(uint32_t& r0, uint32_t& r1, uint32_t& r2,
                                      uint32_t& r3, uint32_t addr) {
    asm volatile("ldmatrix.sync.aligned.m8n8.x4.shared.b16 {%0,%1,%2,%3}, [%4];"
                 : "=r"(r0), "=r"(r1), "=r"(r2), "=r"(r3) : "r"(addr));
}

// ---------------------------------------------------------------------------
// Prep kernels
// ---------------------------------------------------------------------------
__global__ void transpose_rna_k(const float* __restrict__ W, float* __restrict__ Wt) {
    __shared__ float t[32][33];
    const int bx = blockIdx.x * 32, by = blockIdx.y * 32;
    const int x = threadIdx.x;
    #pragma unroll
    for (int j = threadIdx.y; j < 32; j += 8)
        t[j][x] = W[(by + j) * D_DIM + bx + x];
    __syncthreads();
    #pragma unroll
    for (int j = threadIdx.y; j < 32; j += 8)
        Wt[(bx + j) * D_DIM + by + x] = __uint_as_float(f2tf(t[x][j]));
}

// Fused: Ar = rna(A) and s = A @ b. One block per row m.
__global__ void roundrow_k(const float* __restrict__ A, const float* __restrict__ b,
                           float* __restrict__ Ar, float* __restrict__ s) {
    __shared__ float red[8];
    const int m = blockIdx.x;
    const int tid = threadIdx.x;
    float acc = 0.f;
    #pragma unroll
    for (int d = tid; d < D_DIM; d += 256) {
        const float a = A[(size_t)m * D_DIM + d];
        Ar[(size_t)m * D_DIM + d] = __uint_as_float(f2tf(a));
        acc += a * b[d];
    }
    #pragma unroll
    for (int o = 16; o; o >>= 1) acc += __shfl_xor_sync(0xffffffffu, acc, o);
    if ((tid & 31) == 0) red[tid >> 5] = acc;
    __syncthreads();
    if (tid < 8) {
        float v = red[tid];
        #pragma unroll
        for (int o = 4; o; o >>= 1) v += __shfl_xor_sync(0xffu, v, o);
        if (tid == 0) s[m] = v;
    }
}

// E (fp32) -> Eh (fp16), 8 elems/thread
__global__ void convE_k(const float* __restrict__ E, __half* __restrict__ Eh, int n8) {
    int i = blockIdx.x * 256 + threadIdx.x;
    if (i < n8) {
        const float4* p = reinterpret_cast<const float4*>(E) + (size_t)i * 2;
        float4 x = p[0], y = p[1];
        __half2 h0 = __floats2half2_rn(x.x, x.y);
        __half2 h1 = __floats2half2_rn(x.z, x.w);
        __half2 h2 = __floats2half2_rn(y.x, y.y);
        __half2 h3 = __floats2half2_rn(y.z, y.w);
        uint4 o;
        o.x = *reinterpret_cast<uint32_t*>(&h0);
        o.y = *reinterpret_cast<uint32_t*>(&h1);
        o.z = *reinterpret_cast<uint32_t*>(&h2);
        o.w = *reinterpret_cast<uint32_t*>(&h3);
        reinterpret_cast<uint4*>(Eh)[i] = o;
    }
}

// ---------------------------------------------------------------------------
// GEMM1 (tf32): A'h = fp16(Ar @ Wt^T), 64x64 tiles, m16n8k8, LDS.64 relabel.
// 4-stage cp.async pipeline (L2-latency tolerant), single sync per k-tile.
// ---------------------------------------------------------------------------
#define BM1 64
#define BN1 64
#define BK1 32
#define LDS1 40
#define NST1 4
#define STG1F (BM1 * LDS1)            // floats per A stage (== B stage)

__global__ __launch_bounds__(256, 2) void gemm1_tf32_k(
    const float* __restrict__ A, const float* __restrict__ B, __half* __restrict__ C)
{
    extern __shared__ float smem[];
    float* As = smem;                          // [NST1][STG1F]
    float* Bs = smem + NST1 * STG1F;           // [NST1][STG1F]

    const int tid = threadIdx.x;
    const int m0 = blockIdx.x * BM1;
    const int n0 = blockIdx.y * BN1;
    const int KT = D_DIM / BK1;                // 24

    const uint32_t sAs = (uint32_t)__cvta_generic_to_shared(As);
    const uint32_t sBs = (uint32_t)__cvta_generic_to_shared(Bs);

    const int lane = tid & 31;
    const int wid  = tid >> 5;
    const int mb = (wid & 3) * 16;
    const int nb = (wid >> 2) * 32;
    const int lr = lane >> 2;
    const int lc = lane & 3;

    float acc[4][4];
    #pragma unroll
    for (int j = 0; j < 4; j++)
        #pragma unroll
        for (int q = 0; q < 4; q++) acc[j][q] = 0.f;

    auto load_tile = [&](int buf, int kt) {
        const int k0 = kt * BK1;
        #pragma unroll
        for (int it = 0; it < 2; it++) {
            const int c  = tid + it * 256;
            const int r  = c >> 3;
            const int kk = (c & 7) << 2;
            cpasync16(sAs + (uint32_t)(buf * STG1F + r * LDS1 + kk) * 4u,
                      A + (size_t)(m0 + r) * D_DIM + k0 + kk);
            cpasync16(sBs + (uint32_t)(buf * STG1F + r * LDS1 + kk) * 4u,
                      B + (size_t)(n0 + r) * D_DIM + k0 + kk);
        }
    };

    #pragma unroll
    for (int p = 0; p < NST1 - 1; p++) { load_tile(p, p); CP_COMMIT(); }

    for (int kt = 0; kt < KT; kt++) {
        CP_WAIT2();
        __syncthreads();

        const int lt = kt + NST1 - 1;
        if (lt < KT) load_tile(lt & 3, lt);
        CP_COMMIT();

        const float* Ab = As + (kt & 3) * STG1F;
        const float* Bb = Bs + (kt & 3) * STG1F;

        #pragma unroll
        for (int ks = 0; ks < 4; ks++) {
            const int kcol = ks * 8 + 2 * lc;
            uint32_t af[4], bf[4][2];
            {
                const int r = mb + lr;
                const float2 v0 = *reinterpret_cast<const float2*>(&Ab[r * LDS1 + kcol]);
                const float2 v1 = *reinterpret_cast<const float2*>(&Ab[(r + 8) * LDS1 + kcol]);
                af[0] = __float_as_uint(v0.x);
                af[1] = __float_as_uint(v1.x);
                af[2] = __float_as_uint(v0.y);
                af[3] = __float_as_uint(v1.y);
            }
            #pragma unroll
            for (int j = 0; j < 4; j++) {
                const int n = nb + j * 8 + lr;
                const float2 v = *reinterpret_cast<const float2*>(&Bb[n * LDS1 + kcol]);
                bf[j][0] = __float_as_uint(v.x);
                bf[j][1] = __float_as_uint(v.y);
            }
            #pragma unroll
            for (int j = 0; j < 4; j++)
                asm volatile(
                    "mma.sync.aligned.m16n8k8.row.col.f32.tf32.tf32.f32 "
                    "{%0,%1,%2,%3}, {%4,%5,%6,%7}, {%8,%9}, {%0,%1,%2,%3};\n"
                    : "+f"(acc[j][0]), "+f"(acc[j][1]), "+f"(acc[j][2]), "+f"(acc[j][3])
                    : "r"(af[0]), "r"(af[1]), "r"(af[2]), "r"(af[3]),
                      "r"(bf[j][0]), "r"(bf[j][1]));
        }
    }

    const int row0 = m0 + mb + lr;
    const int row1 = row0 + 8;
    #pragma unroll
    for (int j = 0; j < 4; j++) {
        const int col = n0 + nb + j * 8 + 2 * lc;
        *reinterpret_cast<__half2*>(C + (size_t)row0 * D_DIM + col) =
            __floats2half2_rn(acc[j][0], acc[j][1]);
        *reinterpret_cast<__half2*>(C + (size_t)row1 * D_DIM + col) =
            __floats2half2_rn(acc[j][2], acc[j][3]);
    }
}

// ---------------------------------------------------------------------------
// GEMM2 (fp16): out = Ah @ Bh^T + bias. 128x128 tiles, BK=64 halves.
// 3-stage cp.async pipeline; XOR-swizzled 128B rows; ldmatrix.x4; 1 sync/ktile.
// ---------------------------------------------------------------------------
#define BM2 128
#define BN2 128
#define BK2 64
#define NST 3
#define ASTG 16384
#define STG  32768

__global__ __launch_bounds__(256, 2) void gemm2_fp16_k(
    const __half* __restrict__ A, const __half* __restrict__ B,
    float* __restrict__ C, const float* __restrict__ bias, int N)
{
    extern __shared__ __half smh[];
    const uint32_t sb = (uint32_t)__cvta_generic_to_shared(smh);

    const int tid = threadIdx.x;
    const int m0 = blockIdx.x * BM2;
    const int n0 = blockIdx.y * BN2;
    const int KT = D_DIM / BK2;          // 12

    const int lane = tid & 31;
    const int wid  = tid >> 5;
    const int mb = (wid & 3) * 32;
    const int nb = (wid >> 2) * 64;
    const int lr = lane >> 2;
    const int lc = lane & 3;

    const int lrow = lane & 7;
    const int mat  = lane >> 3;
    int aoff[2], arm[2];
    #pragma unroll
    for (int i = 0; i < 2; i++) {
        const int r = mb + i * 16 + ((mat & 1) << 3) + lrow;
        aoff[i] = r * 128;
        arm[i] = r & 7;
    }
    const int acb = mat >> 1;
    int boff[4], brm[4];
    #pragma unroll
    for (int jp = 0; jp < 4; jp++) {
        const int r = nb + (jp * 2 + (mat >> 1)) * 8 + lrow;
        boff[jp] = r * 128;
        brm[jp] = r & 7;
    }
    const int bcb = mat & 1;

    float acc[2][8][4];
    #pragma unroll
    for (int i = 0; i < 2; i++)
        #pragma unroll
        for (int j = 0; j < 8; j++)
            #pragma unroll
            for (int q = 0; q < 4; q++) acc[i][j][q] = 0.f;

    auto load_tile = [&](int buf, int kt) {
        const int k0 = kt * BK2;
        const uint32_t stg = sb + (uint32_t)buf * STG;
        #pragma unroll
        for (int it = 0; it < 4; it++) {
            const int c  = tid + it * 256;
            const int r  = c >> 3;
            const int cc = c & 7;
            const uint32_t soff = (uint32_t)(r * 128 + ((cc ^ (r & 7)) << 4));
            cpasync16(stg + soff, A + (size_t)(m0 + r) * D_DIM + k0 + cc * 8);
            int gr = n0 + r; if (gr >= N) gr = N - 1;
            cpasync16(stg + ASTG + soff, B + (size_t)gr * D_DIM + k0 + cc * 8);
        }
    };

    load_tile(0, 0); CP_COMMIT();
    load_tile(1, 1); CP_COMMIT();

    for (int kt = 0; kt < KT; kt++) {
        CP_WAIT1();
        __syncthreads();

        const int lt = kt + 2;
        if (lt < KT) load_tile(lt % NST, lt);
        CP_COMMIT();

        const uint32_t Ab = sb + (uint32_t)(kt % NST) * STG;
        const uint32_t Bb = Ab + ASTG;

        #pragma unroll
        for (int ks = 0; ks < 4; ks++) {
            uint32_t aq[2][4], bq[4][4];
            #pragma unroll
            for (int i = 0; i < 2; i++)
                ldsm4(aq[i][0], aq[i][1], aq[i][2], aq[i][3],
                      Ab + aoff[i] + (((ks * 2 + acb) ^ arm[i]) << 4));
            #pragma unroll
            for (int jp = 0; jp < 4; jp++)
                ldsm4(bq[jp][0], bq[jp][1], bq[jp][2], bq[jp][3],
                      Bb + boff[jp] + (((ks * 2 + bcb) ^ brm[jp]) << 4));
            #pragma unroll
            for (int i = 0; i < 2; i++)
                #pragma unroll
                for (int j = 0; j < 8; j++) {
                    const uint32_t b0 = bq[j >> 1][(j & 1) * 2];
                    const uint32_t b1 = bq[j >> 1][(j & 1) * 2 + 1];
                    asm volatile(
                        "mma.sync.aligned.m16n8k16.row.col.f32.f16.f16.f32 "
                        "{%0,%1,%2,%3}, {%4,%5,%6,%7}, {%8,%9}, {%0,%1,%2,%3};\n"
                        : "+f"(acc[i][j][0]), "+f"(acc[i][j][1]),
                          "+f"(acc[i][j][2]), "+f"(acc[i][j][3])
                        : "r"(aq[i][0]), "r"(aq[i][1]), "r"(aq[i][2]), "r"(aq[i][3]),
                          "r"(b0), "r"(b1));
                }
        }
    }

    #pragma unroll
    for (int i = 0; i < 2; i++) {
        const int row0 = m0 + mb + i * 16 + lr;
        const int row1 = row0 + 8;
        const float sv0 = bias[row0];
        const float sv1 = bias[row1];
        #pragma unroll
        for (int j = 0; j < 8; j++) {
            const int col = n0 + nb + j * 8 + 2 * lc;
            if (col < N) {
                float2 v0 = make_float2(acc[i][j][0] + sv0, acc[i][j][1] + sv0);
                float2 v1 = make_float2(acc[i][j][2] + sv1, acc[i][j][3] + sv1);
                *reinterpret_cast<float2*>(C + (size_t)row0 * N + col) = v0;
                *reinterpret_cast<float2*>(C + (size_t)row1 * N + col) = v1;
            }
        }
    }
}

// ---------------------------------------------------------------------------
// out = (A@W) @ E^T + (A@b)
// Fork-join: convE on a side stream, overlapped with {transpose,roundrow,gemm1}.
// ---------------------------------------------------------------------------
extern "C" void kernel_launch(void* const* d_in, const int* in_sizes, int n_in,
                              void* d_out, int out_size) {
    const float* A = (const float*)d_in[0];
    const float* E = (const float*)d_in[1];
    const float* W = (const float*)d_in[2];
    const float* b = (const float*)d_in[3];
    float* out = (float*)d_out;

    float *Wt, *Ar, *s;
    __half *Aph, *Eh;
    cudaGetSymbolAddress((void**)&Wt, g_Wt);
    cudaGetSymbolAddress((void**)&Ar, g_Ar);
    cudaGetSymbolAddress((void**)&s, g_s);
    cudaGetSymbolAddress((void**)&Aph, g_Aph);
    cudaGetSymbolAddress((void**)&Eh, g_Eh);

    const int smem1 = NST1 * 2 * STG1F * 4;    // 81920
    const int smem2 = NST * STG;               // 98304
    cudaFuncSetAttribute(gemm1_tf32_k, cudaFuncAttributeMaxDynamicSharedMemorySize, smem1);
    cudaFuncSetAttribute(gemm2_fp16_k, cudaFuncAttributeMaxDynamicSharedMemorySize, smem2);

    // Lazily created once (on the uncaptured correctness call); reused during capture.
    static cudaStream_t s2 = nullptr;
    static cudaEvent_t ef = nullptr, ej = nullptr;
    if (!s2) {
        cudaStreamCreateWithFlags(&s2, cudaStreamNonBlocking);
        cudaEventCreateWithFlags(&ef, cudaEventDisableTiming);
        cudaEventCreateWithFlags(&ej, cudaEventDisableTiming);
    }

    // Fork: convE on side stream
    cudaEventRecord(ef, 0);
    cudaStreamWaitEvent(s2, ef, 0);
    convE_k<<<(V_DIM * D_DIM / 8 + 255) / 256, 256, 0, s2>>>(E, Eh, V_DIM * D_DIM / 8);
    cudaEventRecord(ej, s2);

    // Main chain
    transpose_rna_k<<<dim3(24, 24), dim3(32, 8)>>>(W, Wt);
    roundrow_k<<<M_DIM, 256>>>(A, b, Ar, s);
    gemm1_tf32_k<<<dim3(M_DIM / BM1, D_DIM / BN1), 256, smem1>>>(Ar, Wt, Aph);

    // Join, then gemm2
    cudaStreamWaitEvent(0, ej, 0);
    gemm2_fp16_k<<<dim3(M_DIM / BM2, (V_DIM + BN2 - 1) / BN2), 256, smem2>>>(
        Aph, Eh, out, s, V_DIM);
}